// round 13
// baseline (speedup 1.0000x reference)
#include <cuda_runtime.h>
#include <cuda_bf16.h>

// TabNet encoder on tensor cores: bf16 hi/lo split mma.sync (3-term compensated).
// 2 CTAs per SM, each CTA = 32 rows / 256 threads (8 warps).
// ROUND 12 change: sigmoid is MUFU-free (exp2 poly + Newton reciprocal, all
// FMA/ALU) — removes the hidden ~1.9ms XU-pipe floor (536M MUFU ops).
// B=131072, D=256, UN=128, ND=NA=64, NSTEPS=3.

#define TB 32
#define NTH 256
#define CK 16
#define W_ROWS 1600
#define BMAX 131072

#define WROW_SH0 0
#define WROW_SH1 256
#define WROW_DEP 384
#define WROW_AT  1408

__device__ __nv_bfloat16 g_whi[W_ROWS * 256];
__device__ __nv_bfloat16 g_wlo[W_ROWS * 256];
__device__ float2 g_fold[14 * 256];
__device__ float g_prior[(size_t)BMAX * 256];

// smem layout (bytes), per CTA (110592 total -> 2 CTAs/SM)
#define OFF_MPH 0          // 32 x 264 bf16 = 16896
#define OFF_MPL 16896
#define OFF_GPH 33792      // 32 x 136 bf16 = 8704
#define OFF_GPL 42496
#define OFF_XPH 51200
#define OFF_XPL 59904
#define OFF_AGG 68608      // 32 x 64 f32 = 8192
#define OFF_RING 76800     // 2 bufs x 2 planes x 16x264 bf16 = 33792
#define SMEM_TOTAL 110592

// MUFU-free sigmoid: 1/(1+2^(-x*log2e)) with poly exp2 + Newton reciprocal.
// Max rel err ~1e-7; uses only FMA/ALU pipes.
__device__ __forceinline__ float sig_(float x) {
    float t = fminf(fmaxf(-x * 1.4426950408889634f, -30.0f), 30.0f);
    float n = rintf(t);
    float f = t - n;
    float p = 1.3333558146428443e-3f;
    p = fmaf(p, f, 9.6181291976475699e-3f);
    p = fmaf(p, f, 5.5504108664798463e-2f);
    p = fmaf(p, f, 2.4022650695910071e-1f);
    p = fmaf(p, f, 6.9314718055994531e-1f);
    p = fmaf(p, f, 1.0f);
    float e = __int_as_float(__float_as_int(p) + (((int)n) << 23));  // 2^t
    float d = 1.0f + e;
    float r = __int_as_float(0x7EF34D47 - __float_as_int(d));        // ~5% seed
    r = r * fmaf(-d, r, 2.0f);
    r = r * fmaf(-d, r, 2.0f);
    r = r * fmaf(-d, r, 2.0f);
    return r;
}

__device__ __forceinline__ unsigned sptr(const void* p) {
    return (unsigned)__cvta_generic_to_shared(p);
}
__device__ __forceinline__ void cpa16(unsigned s, const void* g) {
    asm volatile("cp.async.cg.shared.global [%0], [%1], 16;" :: "r"(s), "l"(g));
}
__device__ __forceinline__ void cpa_commit() {
    asm volatile("cp.async.commit_group;" ::: "memory");
}
__device__ __forceinline__ void cpa_wait1() {
    asm volatile("cp.async.wait_group 1;" ::: "memory");
}
__device__ __forceinline__ void ldm4(unsigned a, unsigned& r0, unsigned& r1,
                                     unsigned& r2, unsigned& r3) {
    asm volatile("ldmatrix.sync.aligned.m8n8.x4.shared.b16 {%0,%1,%2,%3},[%4];"
                 : "=r"(r0), "=r"(r1), "=r"(r2), "=r"(r3) : "r"(a));
}
__device__ __forceinline__ void ldm4t(unsigned a, unsigned& r0, unsigned& r1,
                                      unsigned& r2, unsigned& r3) {
    asm volatile("ldmatrix.sync.aligned.m8n8.x4.trans.shared.b16 {%0,%1,%2,%3},[%4];"
                 : "=r"(r0), "=r"(r1), "=r"(r2), "=r"(r3) : "r"(a));
}
__device__ __forceinline__ void mma_bf16(float* d, const unsigned* a, const unsigned* b) {
    asm volatile("mma.sync.aligned.m16n8k16.row.col.f32.bf16.bf16.f32 "
                 "{%0,%1,%2,%3},{%4,%5,%6,%7},{%8,%9},{%0,%1,%2,%3};"
                 : "+f"(d[0]), "+f"(d[1]), "+f"(d[2]), "+f"(d[3])
                 : "r"(a[0]), "r"(a[1]), "r"(a[2]), "r"(a[3]), "r"(b[0]), "r"(b[1]));
}
__device__ __forceinline__ void sts32(unsigned a, unsigned v) {
    asm volatile("st.shared.b32 [%0],%1;" :: "r"(a), "r"(v));
}
__device__ __forceinline__ unsigned lds32(unsigned a) {
    unsigned v; asm volatile("ld.shared.b32 %0,[%1];" : "=r"(v) : "r"(a)); return v;
}
__device__ __forceinline__ void sts16(unsigned a, unsigned short v) {
    asm volatile("st.shared.u16 [%0],%1;" :: "r"(a), "h"(v));
}
__device__ __forceinline__ unsigned short lds16(unsigned a) {
    unsigned short v; asm volatile("ld.shared.u16 %0,[%1];" : "=h"(v) : "r"(a)); return v;
}
__device__ __forceinline__ float bfu(unsigned short u) {
    return __bfloat162float(__ushort_as_bfloat16(u));
}
__device__ __forceinline__ void packsplit(float a, float b, unsigned& hi, unsigned& lo) {
    __nv_bfloat16 ah = __float2bfloat16(a), bh = __float2bfloat16(b);
    float la = a - __bfloat162float(ah), lb = b - __bfloat162float(bh);
    hi = (unsigned)__bfloat16_as_ushort(ah) | ((unsigned)__bfloat16_as_ushort(bh) << 16);
    lo = (unsigned)__bfloat16_as_ushort(__float2bfloat16(la))
       | ((unsigned)__bfloat16_as_ushort(__float2bfloat16(lb)) << 16);
}
__device__ __forceinline__ float2 up_pair(unsigned h, unsigned l) {
    return make_float2(bfu((unsigned short)(h & 0xFFFF)) + bfu((unsigned short)(l & 0xFFFF)),
                       bfu((unsigned short)(h >> 16)) + bfu((unsigned short)(l >> 16)));
}

// ---- prep: split weights to bf16 hi/lo planes; fold BN to (scale,bias) ----
__global__ void prep_kernel(const float* __restrict__ sh_W0, const float* __restrict__ sh_W1,
    const float* __restrict__ dep_W, const float* __restrict__ at_W,
    const float* __restrict__ in_g, const float* __restrict__ in_b,
    const float* __restrict__ in_m, const float* __restrict__ in_v,
    const float* __restrict__ sh_g, const float* __restrict__ sh_b,
    const float* __restrict__ sh_m, const float* __restrict__ sh_v,
    const float* __restrict__ dep_g, const float* __restrict__ dep_b,
    const float* __restrict__ dep_m, const float* __restrict__ dep_v,
    const float* __restrict__ at_g, const float* __restrict__ at_b,
    const float* __restrict__ at_m, const float* __restrict__ at_v)
{
    int tid = blockIdx.x * blockDim.x + threadIdx.x;
    int nthr = gridDim.x * blockDim.x;
    for (int i = tid; i < W_ROWS * 256; i += nthr) {
        int row = i >> 8;
        float w;
        if (row < 256)       w = sh_W0[i];
        else if (row < 384)  w = sh_W1[i - 256 * 256];
        else if (row < 1408) w = dep_W[i - 384 * 256];
        else                 w = at_W[i - 1408 * 256];
        __nv_bfloat16 hi = __float2bfloat16(w);
        g_whi[i] = hi;
        g_wlo[i] = __float2bfloat16(w - __bfloat162float(hi));
    }
    for (int i = tid; i < 14 * 256; i += nthr) {
        int l = i >> 8, c = i & 255;
        float g, b, m, v;
        if (l == 0)       { g = in_g[c]; b = in_b[c]; m = in_m[c]; v = in_v[c]; }
        else if (l <= 2)  { int j = (l - 1) * 256 + c;  g = sh_g[j];  b = sh_b[j];  m = sh_m[j];  v = sh_v[j]; }
        else if (l <= 10) { int j = (l - 3) * 256 + c;  g = dep_g[j]; b = dep_b[j]; m = dep_m[j]; v = dep_v[j]; }
        else              { int j = (l - 11) * 256 + c; g = at_g[j];  b = at_b[j];  m = at_m[j];  v = at_v[j]; }
        float sc = g * rsqrtf(v + 1e-3f);
        g_fold[i] = make_float2(sc, b - m * sc);
    }
}

// ---- GEMM core: A(32xK) @ W(Kx256), bf16 split, 16-k double-buffered ring ----
__device__ __forceinline__ void load_wchunk(int row0, int buf, unsigned ring_s) {
    int t = threadIdx.x;
#pragma unroll
    for (int q = 0; q < 4; q++) {
        int idx = t + NTH * q;               // 0..1023 x 16B
        int plane = idx >> 9;
        int rem = idx & 511;
        int row = rem >> 5, seg = rem & 31;
        const __nv_bfloat16* src = (plane ? g_wlo : g_whi) + (row0 + row) * 256 + seg * 8;
        cpa16(ring_s + buf * 16896 + plane * 8448 + (row * 264 + seg * 8) * 2, src);
    }
}

// 8 warps: warp w owns n-cols {16w..16w+15} and {16w+128..16w+143}.
template<int K>
__device__ __forceinline__ void gemm_core(unsigned a_hi, unsigned a_lo, int strideA,
                                          int wrow0, unsigned ring_s, float (&acc)[2][4][4])
{
    const int lane = threadIdx.x & 31;
    const int w = threadIdx.x >> 5;          // 0..7
    const int l15 = lane & 15;
    const int h8 = (lane >> 4) << 3;
#pragma unroll
    for (int m = 0; m < 2; m++)
#pragma unroll
        for (int n = 0; n < 4; n++)
#pragma unroll
            for (int e = 0; e < 4; e++) acc[m][n][e] = 0.f;

    constexpr int NCH = K / CK;
    load_wchunk(wrow0, 0, ring_s);
    cpa_commit();

#pragma unroll 1
    for (int c = 0; c < NCH; c++) {
        if (c + 1 < NCH) load_wchunk(wrow0 + (c + 1) * CK, (c + 1) & 1, ring_s);
        cpa_commit();
        cpa_wait1();
        __syncthreads();
        unsigned wbh = ring_s + (c & 1) * 16896;
        unsigned wbl = wbh + 8448;

        unsigned bh[4][2], bl[4][2];
        unsigned boff = (unsigned)((l15 * 264 + 16 * w + h8) * 2);
        ldm4t(wbh + boff, bh[0][0], bh[0][1], bh[1][0], bh[1][1]);
        ldm4t(wbh + boff + 256, bh[2][0], bh[2][1], bh[3][0], bh[3][1]);
        ldm4t(wbl + boff, bl[0][0], bl[0][1], bl[1][0], bl[1][1]);
        ldm4t(wbl + boff + 256, bl[2][0], bl[2][1], bl[3][0], bl[3][1]);
#pragma unroll
        for (int m = 0; m < 2; m++) {
            unsigned aoff = (unsigned)(((m * 16 + l15) * strideA + c * CK + h8) * 2);
            unsigned ah[4], al[4];
            ldm4(a_hi + aoff, ah[0], ah[1], ah[2], ah[3]);
            ldm4(a_lo + aoff, al[0], al[1], al[2], al[3]);
#pragma unroll
            for (int nt = 0; nt < 4; nt++) {
                mma_bf16(acc[m][nt], ah, bh[nt]);
                mma_bf16(acc[m][nt], al, bh[nt]);
                mma_bf16(acc[m][nt], ah, bl[nt]);
            }
        }
        __syncthreads();
    }
}

// ---- epilogues ----
template<int MODE>
__device__ __forceinline__ void epi_glu(float (&acc)[2][4][4], int layer,
                                        unsigned gp_hi, unsigned gp_lo,
                                        unsigned xp_hi, unsigned xp_lo,
                                        float* agg, bool addagg)
{
    const int lane = threadIdx.x & 31;
    const int w = threadIdx.x >> 5;
    const int tig = lane & 3, gid = lane >> 2;
    float2 fa[2][2], fb[2][2];
#pragma unroll
    for (int j = 0; j < 2; j++)
#pragma unroll
        for (int e = 0; e < 2; e++) {
            int cc = 16 * w + 8 * j + 2 * tig + e;
            fa[j][e] = g_fold[layer * 256 + cc];
            fb[j][e] = g_fold[layer * 256 + cc + 128];
        }
#pragma unroll
    for (int m = 0; m < 2; m++)
#pragma unroll
        for (int j = 0; j < 2; j++)
#pragma unroll
            for (int hh = 0; hh < 2; hh++) {
                int r = m * 16 + gid + 8 * hh;
                int u0 = 16 * w + 8 * j + 2 * tig;
                float v[2];
#pragma unroll
                for (int e = 0; e < 2; e++) {
                    float ha = fmaf(acc[m][j][hh * 2 + e], fa[j][e].x, fa[j][e].y);
                    float hb = fmaf(acc[m][j + 2][hh * 2 + e], fb[j][e].x, fb[j][e].y);
                    v[e] = ha * sig_(hb);
                }
                unsigned dsth = ((MODE == 0) ? gp_hi : xp_hi) + (r * 136 + u0) * 2;
                unsigned dstl = ((MODE == 0) ? gp_lo : xp_lo) + (r * 136 + u0) * 2;
                if (MODE == 1) {
                    float2 g = up_pair(lds32(gp_hi + (r * 136 + u0) * 2),
                                       lds32(gp_lo + (r * 136 + u0) * 2));
                    v[0] = 0.70710678118654752f * (g.x + v[0]);
                    v[1] = 0.70710678118654752f * (g.y + v[1]);
                } else if (MODE == 2) {
                    float2 x = up_pair(lds32(dsth), lds32(dstl));
                    v[0] = 0.70710678118654752f * (x.x + v[0]);
                    v[1] = 0.70710678118654752f * (x.y + v[1]);
                    if (addagg && u0 < 64) {
                        agg[r * 64 + u0]     += fmaxf(v[0], 0.f);
                        agg[r * 64 + u0 + 1] += fmaxf(v[1], 0.f);
                    }
                }
                unsigned ph, pl;
                packsplit(v[0], v[1], ph, pl);
                sts32(dsth, ph);
                sts32(dstl, pl);
            }
}

__device__ __forceinline__ void epi_logits(float (&acc)[2][4][4], int layer,
                                           unsigned mp_hi, unsigned mp_lo)
{
    const int lane = threadIdx.x & 31;
    const int w = threadIdx.x >> 5;
    const int tig = lane & 3, gid = lane >> 2;
#pragma unroll
    for (int m = 0; m < 2; m++)
#pragma unroll
        for (int nt = 0; nt < 4; nt++) {
            int cn = (nt < 2) ? (16 * w + 8 * nt) : (128 + 16 * w + 8 * (nt - 2));
            int u0 = cn + 2 * tig;
            float2 f0 = g_fold[layer * 256 + u0];
            float2 f1 = g_fold[layer * 256 + u0 + 1];
#pragma unroll
            for (int hh = 0; hh < 2; hh++) {
                int r = m * 16 + gid + 8 * hh;
                float v0 = fmaf(acc[m][nt][hh * 2 + 0], f0.x, f0.y);
                float v1 = fmaf(acc[m][nt][hh * 2 + 1], f1.x, f1.y);
                unsigned ph, pl;
                packsplit(v0, v1, ph, pl);
                sts32(mp_hi + (r * 264 + u0) * 2, ph);
                sts32(mp_lo + (r * 264 + u0) * 2, pl);
            }
        }
}

// sparsemax: z = prior * logits(MP); Michelot; MP <- mask * feat(inputs)
__device__ __forceinline__ void sparsemax_phase(int step, long long rowbase, int B,
                                                unsigned mp_hi, unsigned mp_lo,
                                                const float* __restrict__ inputs)
{
    const int w = threadIdx.x >> 5;          // 0..7 -> 4 rows each
    const int lane = threadIdx.x & 31;
    float2 fin[8];
#pragma unroll
    for (int i = 0; i < 8; i++) fin[i] = g_fold[lane + 32 * i];

#pragma unroll 1
    for (int rr = 0; rr < 4; rr++) {
        int r = w * 4 + rr;
        long long gr = rowbase + r; if (gr >= B) gr = B - 1;
        float* pp = g_prior + gr * 256;
        const float* xin = inputs + gr * 256;

        float pv[8], z[8];
#pragma unroll
        for (int i = 0; i < 8; i++) {
            int e = lane + 32 * i;
            float lg = bfu(lds16(mp_hi + (r * 264 + e) * 2))
                     + bfu(lds16(mp_lo + (r * 264 + e) * 2));
            pv[i] = (step == 0) ? 1.0f : pp[e];
            z[i] = pv[i] * lg;
        }
        unsigned am = 0xFFu;
        float tau = 0.0f;
        for (int it = 0; it < 64; it++) {
            float s = 0.0f, cnt = 0.0f;
#pragma unroll
            for (int i = 0; i < 8; i++)
                if (am & (1u << i)) { s += z[i]; cnt += 1.0f; }
#pragma unroll
            for (int o = 16; o >= 1; o >>= 1) {
                s   += __shfl_xor_sync(0xffffffffu, s, o);
                cnt += __shfl_xor_sync(0xffffffffu, cnt, o);
            }
            tau = __fdividef(s - 1.0f, cnt);
            unsigned na = 0u;
#pragma unroll
            for (int i = 0; i < 8; i++)
                if (z[i] > tau) na |= (1u << i);
            int changed = (na != am);
            am = na;
            if (!__any_sync(0xffffffffu, changed)) break;
        }
#pragma unroll
        for (int i = 0; i < 8; i++) {
            int e = lane + 32 * i;
            float mv = fmaxf(z[i] - tau, 0.0f);
            float feat = fmaf(fin[i].x, xin[e], fin[i].y);
            float o = mv * feat;
            __nv_bfloat16 oh = __float2bfloat16(o);
            sts16(mp_hi + (r * 264 + e) * 2, __bfloat16_as_ushort(oh));
            sts16(mp_lo + (r * 264 + e) * 2,
                  __bfloat16_as_ushort(__float2bfloat16(o - __bfloat162float(oh))));
            if (step < 2) pp[e] = pv[i] * (1.3f - mv);
        }
    }
}

__global__ void __launch_bounds__(NTH, 2)
tabnet_mma(const float* __restrict__ inputs, const float* __restrict__ Wout,
           float* __restrict__ out, int B)
{
    extern __shared__ char sm[];
    const unsigned mp_hi = sptr(sm + OFF_MPH), mp_lo = sptr(sm + OFF_MPL);
    const unsigned gp_hi = sptr(sm + OFF_GPH), gp_lo = sptr(sm + OFF_GPL);
    const unsigned xp_hi = sptr(sm + OFF_XPH), xp_lo = sptr(sm + OFF_XPL);
    float* agg = reinterpret_cast<float*>(sm + OFF_AGG);
    const unsigned ring_s = sptr(sm + OFF_RING);

    const int t = threadIdx.x;
    const long long rowbase = (long long)blockIdx.x * TB;

    // phase 0: feat = BN(input) -> MP planes; agg = 0
    {
        const float4* in4 = reinterpret_cast<const float4*>(inputs);
#pragma unroll
        for (int i = 0; i < 8; i++) {
            int lin = t + NTH * i;           // float4 index over 32 x 64
            int r = lin >> 6, c4 = lin & 63;
            long long gr = rowbase + r; if (gr >= B) gr = B - 1;
            float4 xv = in4[gr * 64 + c4];
            float2 f0 = g_fold[c4 * 4 + 0], f1 = g_fold[c4 * 4 + 1];
            float2 f2 = g_fold[c4 * 4 + 2], f3 = g_fold[c4 * 4 + 3];
            unsigned h01, l01, h23, l23;
            packsplit(fmaf(f0.x, xv.x, f0.y), fmaf(f1.x, xv.y, f1.y), h01, l01);
            packsplit(fmaf(f2.x, xv.z, f2.y), fmaf(f3.x, xv.w, f3.y), h23, l23);
            unsigned base = (unsigned)((r * 264 + c4 * 4) * 2);
            sts32(mp_hi + base, h01); sts32(mp_hi + base + 4, h23);
            sts32(mp_lo + base, l01); sts32(mp_lo + base + 4, l23);
        }
        float4* a4 = reinterpret_cast<float4*>(agg);
#pragma unroll
        for (int i = 0; i < 2; i++)
            a4[t + NTH * i] = make_float4(0.f, 0.f, 0.f, 0.f);
    }
    __syncthreads();

    float acc[2][4][4];

    // initial shared block + dep block
    gemm_core<256>(mp_hi, mp_lo, 264, WROW_SH0, ring_s, acc);
    epi_glu<0>(acc, 1, gp_hi, gp_lo, xp_hi, xp_lo, agg, false);
    __syncthreads();
    gemm_core<128>(gp_hi, gp_lo, 136, WROW_SH1, ring_s, acc);
    epi_glu<1>(acc, 2, gp_hi, gp_lo, xp_hi, xp_lo, agg, false);
    __syncthreads();
#pragma unroll 1
    for (int i = 0; i < 2; i++) {
        gemm_core<128>(xp_hi, xp_lo, 136, WROW_DEP + i * 128, ring_s, acc);
        epi_glu<2>(acc, 3 + i, gp_hi, gp_lo, xp_hi, xp_lo, agg, false);
        __syncthreads();
    }

    // 3 decision steps
#pragma unroll 1
    for (int s = 0; s < 3; s++) {
        gemm_core<64>(xp_hi + 128, xp_lo + 128, 136, WROW_AT + s * 64, ring_s, acc);
        epi_logits(acc, 11 + s, mp_hi, mp_lo);
        __syncthreads();
        sparsemax_phase(s, rowbase, B, mp_hi, mp_lo, inputs);
        __syncthreads();

        gemm_core<256>(mp_hi, mp_lo, 264, WROW_SH0, ring_s, acc);
        epi_glu<0>(acc, 1, gp_hi, gp_lo, xp_hi, xp_lo, agg, false);
        __syncthreads();
        gemm_core<128>(gp_hi, gp_lo, 136, WROW_SH1, ring_s, acc);
        epi_glu<1>(acc, 2, gp_hi, gp_lo, xp_hi, xp_lo, agg, false);
        __syncthreads();
#pragma unroll 1
        for (int i = 0; i < 2; i++) {
            gemm_core<128>(xp_hi, xp_lo, 136, WROW_DEP + ((s + 1) * 2 + i) * 128, ring_s, acc);
            epi_glu<2>(acc, 3 + (s + 1) * 2 + i, gp_hi, gp_lo, xp_hi, xp_lo, agg, i == 1);
            __syncthreads();
        }
    }

    // out = agg @ Wout (64x64), SIMT
    {
        const int c = t & 63;
        const int rg = t >> 6;               // 0..3, 8 rows each
        float acco[8];
#pragma unroll
        for (int rr = 0; rr < 8; rr++) acco[rr] = 0.f;
#pragma unroll 1
        for (int k = 0; k < 64; k++) {
            float wv = Wout[k * 64 + c];
#pragma unroll
            for (int rr = 0; rr < 8; rr++)
                acco[rr] = fmaf(agg[(rg * 8 + rr) * 64 + k], wv, acco[rr]);
        }
#pragma unroll
        for (int rr = 0; rr < 8; rr++) {
            long long gr = rowbase + rg * 8 + rr;
            if (gr < B) out[gr * 64 + c] = acco[rr];
        }
    }
}

extern "C" void kernel_launch(void* const* d_in, const int* in_sizes, int n_in,
                              void* d_out, int out_size)
{
    const float* inputs = (const float*)d_in[0];
    prep_kernel<<<64, 256>>>(
        (const float*)d_in[5], (const float*)d_in[6],   // sh_W0, sh_W1
        (const float*)d_in[11], (const float*)d_in[16], // dep_W, at_W
        (const float*)d_in[1], (const float*)d_in[2], (const float*)d_in[3], (const float*)d_in[4],
        (const float*)d_in[7], (const float*)d_in[8], (const float*)d_in[9], (const float*)d_in[10],
        (const float*)d_in[12], (const float*)d_in[13], (const float*)d_in[14], (const float*)d_in[15],
        (const float*)d_in[17], (const float*)d_in[18], (const float*)d_in[19], (const float*)d_in[20]);

    int B = in_sizes[0] / 256;
    int grid = (B + TB - 1) / TB;
    cudaFuncSetAttribute(tabnet_mma, cudaFuncAttributeMaxDynamicSharedMemorySize, SMEM_TOTAL);
    tabnet_mma<<<grid, NTH, SMEM_TOTAL>>>(inputs, (const float*)d_in[21],
                                          (float*)d_out, B);
}

// round 14
// speedup vs baseline: 1.0425x; 1.0425x over previous
#include <cuda_runtime.h>
#include <cuda_bf16.h>

// TabNet encoder on tensor cores: bf16 hi/lo split mma.sync (3-term compensated).
// 2 CTAs per SM, each CTA = 32 rows / 256 threads (8 warps).
// ROUND 14: single barrier per weight chunk (load issued after the leading
// sync makes the trailing sync redundant); mma outside the protected region;
// sigmoid reverted to MUFU version (round-12 test showed XU is not binding).
// B=131072, D=256, UN=128, ND=NA=64, NSTEPS=3.

#define TB 32
#define NTH 256
#define CK 16
#define W_ROWS 1600
#define BMAX 131072

#define WROW_SH0 0
#define WROW_SH1 256
#define WROW_DEP 384
#define WROW_AT  1408

__device__ __nv_bfloat16 g_whi[W_ROWS * 256];
__device__ __nv_bfloat16 g_wlo[W_ROWS * 256];
__device__ float2 g_fold[14 * 256];
__device__ float g_prior[(size_t)BMAX * 256];

// smem layout (bytes), per CTA (110592 total -> 2 CTAs/SM)
#define OFF_MPH 0          // 32 x 264 bf16 = 16896
#define OFF_MPL 16896
#define OFF_GPH 33792      // 32 x 136 bf16 = 8704
#define OFF_GPL 42496
#define OFF_XPH 51200
#define OFF_XPL 59904
#define OFF_AGG 68608      // 32 x 64 f32 = 8192
#define OFF_RING 76800     // 2 bufs x 2 planes x 16x264 bf16 = 33792
#define SMEM_TOTAL 110592

__device__ __forceinline__ float sig_(float x) {
    return __fdividef(1.0f, 1.0f + __expf(-x));
}
__device__ __forceinline__ unsigned sptr(const void* p) {
    return (unsigned)__cvta_generic_to_shared(p);
}
__device__ __forceinline__ void cpa16(unsigned s, const void* g) {
    asm volatile("cp.async.cg.shared.global [%0], [%1], 16;" :: "r"(s), "l"(g));
}
__device__ __forceinline__ void cpa_commit() {
    asm volatile("cp.async.commit_group;" ::: "memory");
}
__device__ __forceinline__ void cpa_wait0() {
    asm volatile("cp.async.wait_group 0;" ::: "memory");
}
__device__ __forceinline__ void ldm4(unsigned a, unsigned& r0, unsigned& r1,
                                     unsigned& r2, unsigned& r3) {
    asm volatile("ldmatrix.sync.aligned.m8n8.x4.shared.b16 {%0,%1,%2,%3},[%4];"
                 : "=r"(r0), "=r"(r1), "=r"(r2), "=r"(r3) : "r"(a));
}
__device__ __forceinline__ void ldm4t(unsigned a, unsigned& r0, unsigned& r1,
                                      unsigned& r2, unsigned& r3) {
    asm volatile("ldmatrix.sync.aligned.m8n8.x4.trans.shared.b16 {%0,%1,%2,%3},[%4];"
                 : "=r"(r0), "=r"(r1), "=r"(r2), "=r"(r3) : "r"(a));
}
__device__ __forceinline__ void mma_bf16(float* d, const unsigned* a, const unsigned* b) {
    asm volatile("mma.sync.aligned.m16n8k16.row.col.f32.bf16.bf16.f32 "
                 "{%0,%1,%2,%3},{%4,%5,%6,%7},{%8,%9},{%0,%1,%2,%3};"
                 : "+f"(d[0]), "+f"(d[1]), "+f"(d[2]), "+f"(d[3])
                 : "r"(a[0]), "r"(a[1]), "r"(a[2]), "r"(a[3]), "r"(b[0]), "r"(b[1]));
}
__device__ __forceinline__ void sts32(unsigned a, unsigned v) {
    asm volatile("st.shared.b32 [%0],%1;" :: "r"(a), "r"(v));
}
__device__ __forceinline__ unsigned lds32(unsigned a) {
    unsigned v; asm volatile("ld.shared.b32 %0,[%1];" : "=r"(v) : "r"(a)); return v;
}
__device__ __forceinline__ void sts16(unsigned a, unsigned short v) {
    asm volatile("st.shared.u16 [%0],%1;" :: "r"(a), "h"(v));
}
__device__ __forceinline__ unsigned short lds16(unsigned a) {
    unsigned short v; asm volatile("ld.shared.u16 %0,[%1];" : "=h"(v) : "r"(a)); return v;
}
__device__ __forceinline__ float bfu(unsigned short u) {
    return __bfloat162float(__ushort_as_bfloat16(u));
}
__device__ __forceinline__ void packsplit(float a, float b, unsigned& hi, unsigned& lo) {
    __nv_bfloat16 ah = __float2bfloat16(a), bh = __float2bfloat16(b);
    float la = a - __bfloat162float(ah), lb = b - __bfloat162float(bh);
    hi = (unsigned)__bfloat16_as_ushort(ah) | ((unsigned)__bfloat16_as_ushort(bh) << 16);
    lo = (unsigned)__bfloat16_as_ushort(__float2bfloat16(la))
       | ((unsigned)__bfloat16_as_ushort(__float2bfloat16(lb)) << 16);
}
__device__ __forceinline__ float2 up_pair(unsigned h, unsigned l) {
    return make_float2(bfu((unsigned short)(h & 0xFFFF)) + bfu((unsigned short)(l & 0xFFFF)),
                       bfu((unsigned short)(h >> 16)) + bfu((unsigned short)(l >> 16)));
}

// ---- prep: split weights to bf16 hi/lo planes; fold BN to (scale,bias) ----
__global__ void prep_kernel(const float* __restrict__ sh_W0, const float* __restrict__ sh_W1,
    const float* __restrict__ dep_W, const float* __restrict__ at_W,
    const float* __restrict__ in_g, const float* __restrict__ in_b,
    const float* __restrict__ in_m, const float* __restrict__ in_v,
    const float* __restrict__ sh_g, const float* __restrict__ sh_b,
    const float* __restrict__ sh_m, const float* __restrict__ sh_v,
    const float* __restrict__ dep_g, const float* __restrict__ dep_b,
    const float* __restrict__ dep_m, const float* __restrict__ dep_v,
    const float* __restrict__ at_g, const float* __restrict__ at_b,
    const float* __restrict__ at_m, const float* __restrict__ at_v)
{
    int tid = blockIdx.x * blockDim.x + threadIdx.x;
    int nthr = gridDim.x * blockDim.x;
    for (int i = tid; i < W_ROWS * 256; i += nthr) {
        int row = i >> 8;
        float w;
        if (row < 256)       w = sh_W0[i];
        else if (row < 384)  w = sh_W1[i - 256 * 256];
        else if (row < 1408) w = dep_W[i - 384 * 256];
        else                 w = at_W[i - 1408 * 256];
        __nv_bfloat16 hi = __float2bfloat16(w);
        g_whi[i] = hi;
        g_wlo[i] = __float2bfloat16(w - __bfloat162float(hi));
    }
    for (int i = tid; i < 14 * 256; i += nthr) {
        int l = i >> 8, c = i & 255;
        float g, b, m, v;
        if (l == 0)       { g = in_g[c]; b = in_b[c]; m = in_m[c]; v = in_v[c]; }
        else if (l <= 2)  { int j = (l - 1) * 256 + c;  g = sh_g[j];  b = sh_b[j];  m = sh_m[j];  v = sh_v[j]; }
        else if (l <= 10) { int j = (l - 3) * 256 + c;  g = dep_g[j]; b = dep_b[j]; m = dep_m[j]; v = dep_v[j]; }
        else              { int j = (l - 11) * 256 + c; g = at_g[j];  b = at_b[j];  m = at_m[j];  v = at_v[j]; }
        float sc = g * rsqrtf(v + 1e-3f);
        g_fold[i] = make_float2(sc, b - m * sc);
    }
}

// ---- GEMM core: A(32xK) @ W(Kx256), bf16 split, 16-k double-buffered ring ----
__device__ __forceinline__ void load_wchunk(int row0, int buf, unsigned ring_s) {
    int t = threadIdx.x;
#pragma unroll
    for (int q = 0; q < 4; q++) {
        int idx = t + NTH * q;               // 0..1023 x 16B
        int plane = idx >> 9;
        int rem = idx & 511;
        int row = rem >> 5, seg = rem & 31;
        const __nv_bfloat16* src = (plane ? g_wlo : g_whi) + (row0 + row) * 256 + seg * 8;
        cpa16(ring_s + buf * 16896 + plane * 8448 + (row * 264 + seg * 8) * 2, src);
    }
}

// 8 warps: warp w owns n-cols {16w..16w+15} and {16w+128..16w+143}.
// ONE barrier per chunk: load(c+1) is issued after the leading sync, which
// already orders last iteration's ldsm reads of buf (c+1)&1 before the writes.
// mma runs entirely outside the barrier-protected region.
template<int K>
__device__ __forceinline__ void gemm_core(unsigned a_hi, unsigned a_lo, int strideA,
                                          int wrow0, unsigned ring_s, float (&acc)[2][4][4])
{
    const int lane = threadIdx.x & 31;
    const int w = threadIdx.x >> 5;          // 0..7
    const int l15 = lane & 15;
    const int h8 = (lane >> 4) << 3;
#pragma unroll
    for (int m = 0; m < 2; m++)
#pragma unroll
        for (int n = 0; n < 4; n++)
#pragma unroll
            for (int e = 0; e < 4; e++) acc[m][n][e] = 0.f;

    constexpr int NCH = K / CK;
    load_wchunk(wrow0, 0, ring_s);
    cpa_commit();

    const unsigned boff = (unsigned)((l15 * 264 + 16 * w + h8) * 2);

#pragma unroll 1
    for (int c = 0; c < NCH; c++) {
        cpa_wait0();            // chunk c landed (committed last iteration)
        __syncthreads();        // writes visible; also: all warps past ldsm(c-1)
        unsigned wbh = ring_s + (c & 1) * 16896;
        unsigned wbl = wbh + 8448;

        unsigned bh[4][2], bl[4][2];
        ldm4t(wbh + boff, bh[0][0], bh[0][1], bh[1][0], bh[1][1]);
        ldm4t(wbh + boff + 256, bh[2][0], bh[2][1], bh[3][0], bh[3][1]);
        ldm4t(wbl + boff, bl[0][0], bl[0][1], bl[1][0], bl[1][1]);
        ldm4t(wbl + boff + 256, bl[2][0], bl[2][1], bl[3][0], bl[3][1]);
        unsigned ah[2][4], al[2][4];
#pragma unroll
        for (int m = 0; m < 2; m++) {
            unsigned aoff = (unsigned)(((m * 16 + l15) * strideA + c * CK + h8) * 2);
            ldm4(a_hi + aoff, ah[m][0], ah[m][1], ah[m][2], ah[m][3]);
            ldm4(a_lo + aoff, al[m][0], al[m][1], al[m][2], al[m][3]);
        }

        // prefetch next chunk while this chunk's mmas run
        if (c + 1 < NCH) load_wchunk(wrow0 + (c + 1) * CK, (c + 1) & 1, ring_s);
        cpa_commit();

#pragma unroll
        for (int m = 0; m < 2; m++)
#pragma unroll
            for (int nt = 0; nt < 4; nt++) {
                mma_bf16(acc[m][nt], ah[m], bh[nt]);
                mma_bf16(acc[m][nt], al[m], bh[nt]);
                mma_bf16(acc[m][nt], ah[m], bl[nt]);
            }
    }
}

// ---- epilogues ----
template<int MODE>
__device__ __forceinline__ void epi_glu(float (&acc)[2][4][4], int layer,
                                        unsigned gp_hi, unsigned gp_lo,
                                        unsigned xp_hi, unsigned xp_lo,
                                        float* agg, bool addagg)
{
    const int lane = threadIdx.x & 31;
    const int w = threadIdx.x >> 5;
    const int tig = lane & 3, gid = lane >> 2;
    float2 fa[2][2], fb[2][2];
#pragma unroll
    for (int j = 0; j < 2; j++)
#pragma unroll
        for (int e = 0; e < 2; e++) {
            int cc = 16 * w + 8 * j + 2 * tig + e;
            fa[j][e] = g_fold[layer * 256 + cc];
            fb[j][e] = g_fold[layer * 256 + cc + 128];
        }
#pragma unroll
    for (int m = 0; m < 2; m++)
#pragma unroll
        for (int j = 0; j < 2; j++)
#pragma unroll
            for (int hh = 0; hh < 2; hh++) {
                int r = m * 16 + gid + 8 * hh;
                int u0 = 16 * w + 8 * j + 2 * tig;
                float v[2];
#pragma unroll
                for (int e = 0; e < 2; e++) {
                    float ha = fmaf(acc[m][j][hh * 2 + e], fa[j][e].x, fa[j][e].y);
                    float hb = fmaf(acc[m][j + 2][hh * 2 + e], fb[j][e].x, fb[j][e].y);
                    v[e] = ha * sig_(hb);
                }
                unsigned dsth = ((MODE == 0) ? gp_hi : xp_hi) + (r * 136 + u0) * 2;
                unsigned dstl = ((MODE == 0) ? gp_lo : xp_lo) + (r * 136 + u0) * 2;
                if (MODE == 1) {
                    float2 g = up_pair(lds32(gp_hi + (r * 136 + u0) * 2),
                                       lds32(gp_lo + (r * 136 + u0) * 2));
                    v[0] = 0.70710678118654752f * (g.x + v[0]);
                    v[1] = 0.70710678118654752f * (g.y + v[1]);
                } else if (MODE == 2) {
                    float2 x = up_pair(lds32(dsth), lds32(dstl));
                    v[0] = 0.70710678118654752f * (x.x + v[0]);
                    v[1] = 0.70710678118654752f * (x.y + v[1]);
                    if (addagg && u0 < 64) {
                        agg[r * 64 + u0]     += fmaxf(v[0], 0.f);
                        agg[r * 64 + u0 + 1] += fmaxf(v[1], 0.f);
                    }
                }
                unsigned ph, pl;
                packsplit(v[0], v[1], ph, pl);
                sts32(dsth, ph);
                sts32(dstl, pl);
            }
}

__device__ __forceinline__ void epi_logits(float (&acc)[2][4][4], int layer,
                                           unsigned mp_hi, unsigned mp_lo)
{
    const int lane = threadIdx.x & 31;
    const int w = threadIdx.x >> 5;
    const int tig = lane & 3, gid = lane >> 2;
#pragma unroll
    for (int m = 0; m < 2; m++)
#pragma unroll
        for (int nt = 0; nt < 4; nt++) {
            int cn = (nt < 2) ? (16 * w + 8 * nt) : (128 + 16 * w + 8 * (nt - 2));
            int u0 = cn + 2 * tig;
            float2 f0 = g_fold[layer * 256 + u0];
            float2 f1 = g_fold[layer * 256 + u0 + 1];
#pragma unroll
            for (int hh = 0; hh < 2; hh++) {
                int r = m * 16 + gid + 8 * hh;
                float v0 = fmaf(acc[m][nt][hh * 2 + 0], f0.x, f0.y);
                float v1 = fmaf(acc[m][nt][hh * 2 + 1], f1.x, f1.y);
                unsigned ph, pl;
                packsplit(v0, v1, ph, pl);
                sts32(mp_hi + (r * 264 + u0) * 2, ph);
                sts32(mp_lo + (r * 264 + u0) * 2, pl);
            }
        }
}

// sparsemax: z = prior * logits(MP); Michelot; MP <- mask * feat(inputs)
__device__ __forceinline__ void sparsemax_phase(int step, long long rowbase, int B,
                                                unsigned mp_hi, unsigned mp_lo,
                                                const float* __restrict__ inputs)
{
    const int w = threadIdx.x >> 5;          // 0..7 -> 4 rows each
    const int lane = threadIdx.x & 31;
    float2 fin[8];
#pragma unroll
    for (int i = 0; i < 8; i++) fin[i] = g_fold[lane + 32 * i];

#pragma unroll 1
    for (int rr = 0; rr < 4; rr++) {
        int r = w * 4 + rr;
        long long gr = rowbase + r; if (gr >= B) gr = B - 1;
        float* pp = g_prior + gr * 256;
        const float* xin = inputs + gr * 256;

        float pv[8], z[8];
#pragma unroll
        for (int i = 0; i < 8; i++) {
            int e = lane + 32 * i;
            float lg = bfu(lds16(mp_hi + (r * 264 + e) * 2))
                     + bfu(lds16(mp_lo + (r * 264 + e) * 2));
            pv[i] = (step == 0) ? 1.0f : pp[e];
            z[i] = pv[i] * lg;
        }
        unsigned am = 0xFFu;
        float tau = 0.0f;
        for (int it = 0; it < 64; it++) {
            float s = 0.0f, cnt = 0.0f;
#pragma unroll
            for (int i = 0; i < 8; i++)
                if (am & (1u << i)) { s += z[i]; cnt += 1.0f; }
#pragma unroll
            for (int o = 16; o >= 1; o >>= 1) {
                s   += __shfl_xor_sync(0xffffffffu, s, o);
                cnt += __shfl_xor_sync(0xffffffffu, cnt, o);
            }
            tau = __fdividef(s - 1.0f, cnt);
            unsigned na = 0u;
#pragma unroll
            for (int i = 0; i < 8; i++)
                if (z[i] > tau) na |= (1u << i);
            int changed = (na != am);
            am = na;
            if (!__any_sync(0xffffffffu, changed)) break;
        }
#pragma unroll
        for (int i = 0; i < 8; i++) {
            int e = lane + 32 * i;
            float mv = fmaxf(z[i] - tau, 0.0f);
            float feat = fmaf(fin[i].x, xin[e], fin[i].y);
            float o = mv * feat;
            __nv_bfloat16 oh = __float2bfloat16(o);
            sts16(mp_hi + (r * 264 + e) * 2, __bfloat16_as_ushort(oh));
            sts16(mp_lo + (r * 264 + e) * 2,
                  __bfloat16_as_ushort(__float2bfloat16(o - __bfloat162float(oh))));
            if (step < 2) pp[e] = pv[i] * (1.3f - mv);
        }
    }
}

__global__ void __launch_bounds__(NTH, 2)
tabnet_mma(const float* __restrict__ inputs, const float* __restrict__ Wout,
           float* __restrict__ out, int B)
{
    extern __shared__ char sm[];
    const unsigned mp_hi = sptr(sm + OFF_MPH), mp_lo = sptr(sm + OFF_MPL);
    const unsigned gp_hi = sptr(sm + OFF_GPH), gp_lo = sptr(sm + OFF_GPL);
    const unsigned xp_hi = sptr(sm + OFF_XPH), xp_lo = sptr(sm + OFF_XPL);
    float* agg = reinterpret_cast<float*>(sm + OFF_AGG);
    const unsigned ring_s = sptr(sm + OFF_RING);

    const int t = threadIdx.x;
    const long long rowbase = (long long)blockIdx.x * TB;

    // phase 0: feat = BN(input) -> MP planes; agg = 0
    {
        const float4* in4 = reinterpret_cast<const float4*>(inputs);
#pragma unroll
        for (int i = 0; i < 8; i++) {
            int lin = t + NTH * i;           // float4 index over 32 x 64
            int r = lin >> 6, c4 = lin & 63;
            long long gr = rowbase + r; if (gr >= B) gr = B - 1;
            float4 xv = in4[gr * 64 + c4];
            float2 f0 = g_fold[c4 * 4 + 0], f1 = g_fold[c4 * 4 + 1];
            float2 f2 = g_fold[c4 * 4 + 2], f3 = g_fold[c4 * 4 + 3];
            unsigned h01, l01, h23, l23;
            packsplit(fmaf(f0.x, xv.x, f0.y), fmaf(f1.x, xv.y, f1.y), h01, l01);
            packsplit(fmaf(f2.x, xv.z, f2.y), fmaf(f3.x, xv.w, f3.y), h23, l23);
            unsigned base = (unsigned)((r * 264 + c4 * 4) * 2);
            sts32(mp_hi + base, h01); sts32(mp_hi + base + 4, h23);
            sts32(mp_lo + base, l01); sts32(mp_lo + base + 4, l23);
        }
        float4* a4 = reinterpret_cast<float4*>(agg);
#pragma unroll
        for (int i = 0; i < 2; i++)
            a4[t + NTH * i] = make_float4(0.f, 0.f, 0.f, 0.f);
    }
    __syncthreads();

    float acc[2][4][4];

    // initial shared block + dep block
    gemm_core<256>(mp_hi, mp_lo, 264, WROW_SH0, ring_s, acc);
    epi_glu<0>(acc, 1, gp_hi, gp_lo, xp_hi, xp_lo, agg, false);
    __syncthreads();
    gemm_core<128>(gp_hi, gp_lo, 136, WROW_SH1, ring_s, acc);
    epi_glu<1>(acc, 2, gp_hi, gp_lo, xp_hi, xp_lo, agg, false);
    __syncthreads();
#pragma unroll 1
    for (int i = 0; i < 2; i++) {
        gemm_core<128>(xp_hi, xp_lo, 136, WROW_DEP + i * 128, ring_s, acc);
        epi_glu<2>(acc, 3 + i, gp_hi, gp_lo, xp_hi, xp_lo, agg, false);
        __syncthreads();
    }

    // 3 decision steps
#pragma unroll 1
    for (int s = 0; s < 3; s++) {
        gemm_core<64>(xp_hi + 128, xp_lo + 128, 136, WROW_AT + s * 64, ring_s, acc);
        epi_logits(acc, 11 + s, mp_hi, mp_lo);
        __syncthreads();
        sparsemax_phase(s, rowbase, B, mp_hi, mp_lo, inputs);
        __syncthreads();

        gemm_core<256>(mp_hi, mp_lo, 264, WROW_SH0, ring_s, acc);
        epi_glu<0>(acc, 1, gp_hi, gp_lo, xp_hi, xp_lo, agg, false);
        __syncthreads();
        gemm_core<128>(gp_hi, gp_lo, 136, WROW_SH1, ring_s, acc);
        epi_glu<1>(acc, 2, gp_hi, gp_lo, xp_hi, xp_lo, agg, false);
        __syncthreads();
#pragma unroll 1
        for (int i = 0; i < 2; i++) {
            gemm_core<128>(xp_hi, xp_lo, 136, WROW_DEP + ((s + 1) * 2 + i) * 128, ring_s, acc);
            epi_glu<2>(acc, 3 + (s + 1) * 2 + i, gp_hi, gp_lo, xp_hi, xp_lo, agg, i == 1);
            __syncthreads();
        }
    }

    // out = agg @ Wout (64x64), SIMT
    {
        const int c = t & 63;
        const int rg = t >> 6;               // 0..3, 8 rows each
        float acco[8];
#pragma unroll
        for (int rr = 0; rr < 8; rr++) acco[rr] = 0.f;
#pragma unroll 1
        for (int k = 0; k < 64; k++) {
            float wv = Wout[k * 64 + c];
#pragma unroll
            for (int rr = 0; rr < 8; rr++)
                acco[rr] = fmaf(agg[(rg * 8 + rr) * 64 + k], wv, acco[rr]);
        }
#pragma unroll
        for (int rr = 0; rr < 8; rr++) {
            long long gr = rowbase + rg * 8 + rr;
            if (gr < B) out[gr * 64 + c] = acco[rr];
        }
    }
}

extern "C" void kernel_launch(void* const* d_in, const int* in_sizes, int n_in,
                              void* d_out, int out_size)
{
    const float* inputs = (const float*)d_in[0];
    prep_kernel<<<64, 256>>>(
        (const float*)d_in[5], (const float*)d_in[6],   // sh_W0, sh_W1
        (const float*)d_in[11], (const float*)d_in[16], // dep_W, at_W
        (const float*)d_in[1], (const float*)d_in[2], (const float*)d_in[3], (const float*)d_in[4],
        (const float*)d_in[7], (const float*)d_in[8], (const float*)d_in[9], (const float*)d_in[10],
        (const float*)d_in[12], (const float*)d_in[13], (const float*)d_in[14], (const float*)d_in[15],
        (const float*)d_in[17], (const float*)d_in[18], (const float*)d_in[19], (const float*)d_in[20]);

    int B = in_sizes[0] / 256;
    int grid = (B + TB - 1) / TB;
    cudaFuncSetAttribute(tabnet_mma, cudaFuncAttributeMaxDynamicSharedMemorySize, SMEM_TOTAL);
    tabnet_mma<<<grid, NTH, SMEM_TOTAL>>>(inputs, (const float*)d_in[21],
                                          (float*)d_out, B);
}